// round 1
// baseline (speedup 1.0000x reference)
#include <cuda_runtime.h>
#include <cuda_bf16.h>
#include <math.h>

#define BATCH 2
#define SEQL 2000
#define DM 256
#define DI 512
#define DS 16
#define RNK 16
#define NX 48          // RNK + 2*DS
#define NROWS (BATCH*SEQL)   // 4000

// ---------------- scratch (device globals; no allocations) ----------------
__device__ float g_h[NROWS*DM];      // residual stream
__device__ float g_ln[NROWS*DM];     // layernorm output
__device__ float g_xz[NROWS*2*DI];   // in_proj output (u | z)
__device__ float g_u[NROWS*DI];      // conv+silu output
__device__ float g_xdbc[NROWS*NX];   // x_proj output (dt_r | B | C)
__device__ float g_dt[NROWS*DI];     // softplus(dt)
__device__ float g_y[NROWS*DI];      // scan output (gated)

// ---------------- helpers ----------------
__device__ __forceinline__ float siluf(float x) {
    return x * __frcp_rn(1.f + __expf(-x));
}
__device__ __forceinline__ float softplusf(float x) {
    return (x > 20.f) ? x : log1pf(__expf(x));
}

// ---------------- embed: h = x*w + b + gene_emb + mod_emb ----------------
__global__ void embed_kernel(const float* __restrict__ x,
                             const float* __restrict__ bw,
                             const float* __restrict__ bb,
                             const float* __restrict__ ge,
                             const float* __restrict__ me) {
    int idx = blockIdx.x * blockDim.x + threadIdx.x;
    if (idx >= NROWS * DM) return;
    int d = idx & (DM - 1);
    int row = idx >> 8;            // b*L + l
    int l = row % SEQL;
    g_h[idx] = x[row] * bw[d] + bb[d] + ge[l * DM + d] + me[d];
}

// ---------------- layernorm: one row (256 cols) per block ----------------
__global__ void ln_kernel(const float* __restrict__ X,
                          const float* __restrict__ w,
                          const float* __restrict__ b,
                          float* __restrict__ Y) {
    __shared__ float sb1[8], sb2[8];
    int row = blockIdx.x;
    int d = threadIdx.x;
    float v = X[row * DM + d];
    float s1 = v, s2 = v * v;
    #pragma unroll
    for (int o = 16; o > 0; o >>= 1) {
        s1 += __shfl_xor_sync(0xffffffffu, s1, o);
        s2 += __shfl_xor_sync(0xffffffffu, s2, o);
    }
    int lane = d & 31, wid = d >> 5;
    if (lane == 0) { sb1[wid] = s1; sb2[wid] = s2; }
    __syncthreads();
    if (wid == 0) {
        float t1 = (lane < 8) ? sb1[lane] : 0.f;
        float t2 = (lane < 8) ? sb2[lane] : 0.f;
        #pragma unroll
        for (int o = 4; o > 0; o >>= 1) {
            t1 += __shfl_xor_sync(0xffffffffu, t1, o);
            t2 += __shfl_xor_sync(0xffffffffu, t2, o);
        }
        if (lane == 0) { sb1[0] = t1; sb2[0] = t2; }
    }
    __syncthreads();
    float mu = sb1[0] * (1.f / DM);
    float var = sb2[0] * (1.f / DM) - mu * mu;
    Y[row * DM + d] = (v - mu) * rsqrtf(var + 1e-5f) * w[d] + b[d];
}

// ---------------- generic SGEMM: C[M,N] = A[M,K] * W[N,K]^T (+ residual) ----------------
#define BM 64
#define BN 64
#define BK 16
__global__ void __launch_bounds__(256) gemm_nt(const float* __restrict__ A,
                                               const float* __restrict__ W,
                                               float* __restrict__ C,
                                               const float* __restrict__ res,
                                               int M, int N, int K) {
    __shared__ float As[BK][BM];
    __shared__ float Bs[BK][BN];
    int tx = threadIdx.x & 15, ty = threadIdx.x >> 4;     // 16x16 grid of threads
    int m0 = blockIdx.y * BM, n0 = blockIdx.x * BN;
    int lr = threadIdx.x >> 2;                            // 0..63 tile row
    int lc = (threadIdx.x & 3) << 2;                      // 0,4,8,12 k-col
    float acc[4][4] = {};
    for (int k0 = 0; k0 < K; k0 += BK) {
        float4 av = make_float4(0.f, 0.f, 0.f, 0.f);
        int ar = m0 + lr;
        if (ar < M) av = *(const float4*)(A + (size_t)ar * K + k0 + lc);
        As[lc + 0][lr] = av.x; As[lc + 1][lr] = av.y;
        As[lc + 2][lr] = av.z; As[lc + 3][lr] = av.w;
        float4 bv = make_float4(0.f, 0.f, 0.f, 0.f);
        int br = n0 + lr;
        if (br < N) bv = *(const float4*)(W + (size_t)br * K + k0 + lc);
        Bs[lc + 0][lr] = bv.x; Bs[lc + 1][lr] = bv.y;
        Bs[lc + 2][lr] = bv.z; Bs[lc + 3][lr] = bv.w;
        __syncthreads();
        #pragma unroll
        for (int kk = 0; kk < BK; kk++) {
            float4 a4 = *(const float4*)&As[kk][ty << 2];
            float4 b4 = *(const float4*)&Bs[kk][tx << 2];
            float ar4[4] = {a4.x, a4.y, a4.z, a4.w};
            float br4[4] = {b4.x, b4.y, b4.z, b4.w};
            #pragma unroll
            for (int i = 0; i < 4; i++)
                #pragma unroll
                for (int j = 0; j < 4; j++)
                    acc[i][j] = fmaf(ar4[i], br4[j], acc[i][j]);
        }
        __syncthreads();
    }
    #pragma unroll
    for (int i = 0; i < 4; i++) {
        int r = m0 + (ty << 2) + i;
        if (r >= M) continue;
        #pragma unroll
        for (int j = 0; j < 4; j++) {
            int c = n0 + (tx << 2) + j;
            if (c >= N) continue;
            float v = acc[i][j];
            if (res) v += res[(size_t)r * N + c];
            C[(size_t)r * N + c] = v;
        }
    }
}

// ---------------- causal depthwise conv (taps=4) + silu ----------------
__global__ void conv_silu_kernel(const float* __restrict__ cw,
                                 const float* __restrict__ cb) {
    int idx = blockIdx.x * blockDim.x + threadIdx.x;
    if (idx >= NROWS * DI) return;
    int d = idx & (DI - 1);
    int row = idx >> 9;            // b*L + l
    int l = row % SEQL;
    float acc = cb[d];
    #pragma unroll
    for (int k = 0; k < 4; k++) {
        int ls = l + k - 3;
        if (ls >= 0)
            acc = fmaf(g_xz[(size_t)(row + k - 3) * (2 * DI) + d], cw[d * 4 + k], acc);
    }
    g_u[idx] = siluf(acc);
}

// ---------------- dt = softplus(dt_r @ dtw^T + b)  (K = 16) ----------------
__global__ void dt_kernel(const float* __restrict__ dtw,
                          const float* __restrict__ dtb) {
    __shared__ float s[RNK];
    int row = blockIdx.x;
    int d = threadIdx.x;           // 512 threads
    if (d < RNK) s[d] = g_xdbc[row * NX + d];
    __syncthreads();
    float acc = dtb[d];
    #pragma unroll
    for (int r = 0; r < RNK; r++)
        acc = fmaf(s[r], dtw[d * RNK + r], acc);
    g_dt[row * DI + d] = softplusf(acc);
}

// ---------------- selective scan (+ D skip + silu(z) gating) ----------------
// 128 blocks x 128 threads; 16 lanes per channel (one per state), 8 channels/block.
__global__ void __launch_bounds__(128, 1) scan_kernel(const float* __restrict__ A_log,
                                                      const float* __restrict__ Dvec) {
    const int tid = threadIdx.x;
    const int g = tid >> 4, n = tid & 15;
    const int b = blockIdx.x >> 6;
    const int d = ((blockIdx.x & 63) << 3) + g;
    const float a = -__expf(A_log[d * DS + n]);
    const float Dv = Dvec[d];
    float hst = 0.f;
    const int rowbase = b * SEQL;

    float pdt[8], pu[8], pz[8], pB[8], pC[8];
    #pragma unroll
    for (int i = 0; i < 8; i++) {
        int base = rowbase + i;
        pdt[i] = g_dt[(size_t)base * DI + d];
        pu[i]  = g_u[(size_t)base * DI + d];
        pz[i]  = g_xz[(size_t)base * (2 * DI) + DI + d];
        pB[i]  = g_xdbc[base * NX + RNK + n];
        pC[i]  = g_xdbc[base * NX + RNK + DS + n];
    }
    for (int tb = 0; tb < SEQL; tb += 8) {
        float cdt[8], cu[8], cz[8], cB[8], cC[8];
        #pragma unroll
        for (int i = 0; i < 8; i++) {
            cdt[i] = pdt[i]; cu[i] = pu[i]; cz[i] = pz[i]; cB[i] = pB[i]; cC[i] = pC[i];
        }
        if (tb + 8 < SEQL) {
            #pragma unroll
            for (int i = 0; i < 8; i++) {
                int base = rowbase + tb + 8 + i;
                pdt[i] = g_dt[(size_t)base * DI + d];
                pu[i]  = g_u[(size_t)base * DI + d];
                pz[i]  = g_xz[(size_t)base * (2 * DI) + DI + d];
                pB[i]  = g_xdbc[base * NX + RNK + n];
                pC[i]  = g_xdbc[base * NX + RNK + DS + n];
            }
        }
        // off-chain: exponentials and input products
        float e[8], duB[8];
        #pragma unroll
        for (int i = 0; i < 8; i++) {
            e[i]   = __expf(cdt[i] * a);
            duB[i] = cdt[i] * cu[i] * cB[i];
        }
        // recurrence chain: one FMA per step
        float part[8];
        #pragma unroll
        for (int i = 0; i < 8; i++) {
            hst = fmaf(e[i], hst, duB[i]);
            part[i] = hst * cC[i];
        }
        // 8 interleaved reduce chains over the 16-lane state group
        #pragma unroll
        for (int off = 8; off; off >>= 1)
            #pragma unroll
            for (int i = 0; i < 8; i++)
                part[i] += __shfl_xor_sync(0xffffffffu, part[i], off, 16);
        if (n == 0) {
            #pragma unroll
            for (int i = 0; i < 8; i++) {
                float yv = part[i] + cu[i] * Dv;
                g_y[(size_t)(rowbase + tb + i) * DI + d] = yv * siluf(cz[i]);
            }
        }
    }
}

// ---------------- head: out[row] = dot(ln_row, head_w) + head_b ----------------
__global__ void head_kernel(const float* __restrict__ hw,
                            const float* __restrict__ hb,
                            float* __restrict__ out) {
    __shared__ float sb[8];
    int row = blockIdx.x;
    int d = threadIdx.x;
    float v = g_ln[row * DM + d] * hw[d];
    #pragma unroll
    for (int o = 16; o > 0; o >>= 1) v += __shfl_xor_sync(0xffffffffu, v, o);
    int lane = d & 31, wid = d >> 5;
    if (lane == 0) sb[wid] = v;
    __syncthreads();
    if (wid == 0) {
        float t = (lane < 8) ? sb[lane] : 0.f;
        #pragma unroll
        for (int o = 4; o > 0; o >>= 1) t += __shfl_xor_sync(0xffffffffu, t, o);
        if (lane == 0) out[row] = t + hb[0];
    }
}

// ---------------- host orchestration ----------------
extern "C" void kernel_launch(void* const* d_in, const int* in_sizes, int n_in,
                              void* d_out, int out_size) {
    const float* x    = (const float*)d_in[0];
    const float* bw   = (const float*)d_in[1];
    const float* bb   = (const float*)d_in[2];
    const float* ge   = (const float*)d_in[3];
    const float* me   = (const float*)d_in[4];
    const float* lnw  = (const float*)d_in[5];
    const float* lnb  = (const float*)d_in[6];
    const float* ipw  = (const float*)d_in[7];
    const float* cw   = (const float*)d_in[8];
    const float* cb   = (const float*)d_in[9];
    const float* xpw  = (const float*)d_in[10];
    const float* dtw  = (const float*)d_in[11];
    const float* dtb  = (const float*)d_in[12];
    const float* alog = (const float*)d_in[13];
    const float* Dv   = (const float*)d_in[14];
    const float* opw  = (const float*)d_in[15];
    const float* fw   = (const float*)d_in[16];
    const float* fb   = (const float*)d_in[17];
    const float* hw   = (const float*)d_in[18];
    const float* hb   = (const float*)d_in[19];
    float* out = (float*)d_out;

    float *p_h, *p_ln, *p_xz, *p_u, *p_xdbc, *p_y;
    cudaGetSymbolAddress((void**)&p_h, g_h);
    cudaGetSymbolAddress((void**)&p_ln, g_ln);
    cudaGetSymbolAddress((void**)&p_xz, g_xz);
    cudaGetSymbolAddress((void**)&p_u, g_u);
    cudaGetSymbolAddress((void**)&p_xdbc, g_xdbc);
    cudaGetSymbolAddress((void**)&p_y, g_y);

    embed_kernel<<<(NROWS * DM + 255) / 256, 256>>>(x, bw, bb, ge, me);

    for (int i = 0; i < 4; i++) {
        ln_kernel<<<NROWS, DM>>>(p_h, lnw + i * DM, lnb + i * DM, p_ln);
        {   // in_proj: 4000x1024x256
            dim3 grid((2 * DI + BN - 1) / BN, (NROWS + BM - 1) / BM);
            gemm_nt<<<grid, 256>>>(p_ln, ipw + (size_t)i * 2 * DI * DM, p_xz,
                                   nullptr, NROWS, 2 * DI, DM);
        }
        conv_silu_kernel<<<(NROWS * DI + 255) / 256, 256>>>(cw + i * DI * 4, cb + i * DI);
        {   // x_proj: 4000x48x512
            dim3 grid((NX + BN - 1) / BN, (NROWS + BM - 1) / BM);
            gemm_nt<<<grid, 256>>>(p_u, xpw + (size_t)i * NX * DI, p_xdbc,
                                   nullptr, NROWS, NX, DI);
        }
        dt_kernel<<<NROWS, DI>>>(dtw + (size_t)i * DI * RNK, dtb + i * DI);
        scan_kernel<<<128, 128>>>(alog + (size_t)i * DI * DS, Dv + i * DI);
        {   // out_proj + residual: 4000x256x512
            dim3 grid((DM + BN - 1) / BN, (NROWS + BM - 1) / BM);
            gemm_nt<<<grid, 256>>>(p_y, opw + (size_t)i * DM * DI, p_h,
                                   p_h, NROWS, DM, DI);
        }
    }

    ln_kernel<<<NROWS, DM>>>(p_h, fw, fb, p_ln);
    head_kernel<<<NROWS, DM>>>(hw, hb, out);
}